// round 1
// baseline (speedup 1.0000x reference)
#include <cuda_runtime.h>
#include <cuda_bf16.h>
#include <cstdint>

#define BATCH 4096
#define OBS 16
#define TDEC 32
#define H 512
#define NG 2048          // 4*H gate columns
#define KTOT 1536        // split-K: [h_hi | h_hi | h_lo]
#define BM 128
#define BN 128
#define BK 32
#define NCHUNK (KTOT / BK)   // 48
#define LDT 40               // padded smem row length (bf16 elems) -> 80B stride, conflict-free
#define TILE_ELEMS (128 * LDT)
#define TILE_BYTES (TILE_ELEMS * 2)      // 10240
#define DYN_SMEM 67584                   // 128 * 132 * 4 for fp32 gate staging (union w/ tiles)

// ---------------- device state (no cudaMalloc allowed) ----------------
__device__ __align__(16) float          g_h[2][BATCH * H];
__device__ __align__(16) float          g_c[2][BATCH * H];
__device__ __align__(16) __nv_bfloat16  g_hhi[2][2][BATCH * H];   // [slot][parity]
__device__ __align__(16) __nv_bfloat16  g_hlo[2][2][BATCH * H];
__device__ __align__(16) __nv_bfloat16  g_Ws[4][NG * 1024];       // [lstm][(4u+gate)*1024 + k] cols: [0,512)=hi, [512,1024)=lo
__device__ __align__(16) float          g_Wi[4][NG * 4];          // permuted
__device__ __align__(16) float          g_bb[4][NG];              // permuted
__device__ __align__(16) float          g_ls[BATCH * 4];
__device__ __align__(16) float          g_lp[BATCH * 4];

// ---------------- helpers ----------------
__device__ __forceinline__ unsigned su32(const void* p) {
    return (unsigned)__cvta_generic_to_shared(p);
}
__device__ __forceinline__ void cp16(unsigned d, const void* s) {
    asm volatile("cp.async.cg.shared.global [%0], [%1], 16;" :: "r"(d), "l"(s));
}
__device__ __forceinline__ float sigf(float x) { return 1.f / (1.f + __expf(-x)); }
__device__ __forceinline__ float tanhfast(float x) { return 2.f / (1.f + __expf(-2.f * x)) - 1.f; }

// ---------------- weight prep: split to bf16 hi/lo + gate-interleave permute ----------------
struct WPtrs { const float* Wh[4]; const float* Wi[4]; const float* bb[4]; };

__global__ void prep_weights(WPtrs p) {
    int k = threadIdx.x;        // 0..511
    int j = blockIdx.x;         // 0..2047 original gate row
    int l = blockIdx.y;         // 0..3 lstm id
    float w = p.Wh[l][j * H + k];
    __nv_bfloat16 hi = __float2bfloat16(w);
    __nv_bfloat16 lo = __float2bfloat16(w - __bfloat162float(hi));
    int pr = 4 * (j & (H - 1)) + (j >> 9);   // 4u + gate
    g_Ws[l][pr * 1024 + k] = hi;
    g_Ws[l][pr * 1024 + 512 + k] = lo;
    if (k < 4)  g_Wi[l][pr * 4 + k] = p.Wi[l][j * 4 + k];
    if (k == 0) g_bb[l][pr] = p.bb[l][j];
}

// ---------------- init: zero states, seed feedback with last observation ----------------
__global__ void init_state(const float* speed, const float* pos) {
    int idx = blockIdx.x * blockDim.x + threadIdx.x;
    if (idx < 2 * BATCH * H) {
        int s = idx / (BATCH * H);
        int i = idx % (BATCH * H);
        g_h[s][i] = 0.f;
        g_c[s][i] = 0.f;
        g_hhi[s][0][i] = __float2bfloat16(0.f);
        g_hlo[s][0][i] = __float2bfloat16(0.f);
    }
    if (idx < BATCH * 4) {
        int b = idx >> 2, k = idx & 3;
        g_ls[idx] = speed[b * (OBS * 4) + (OBS - 1) * 4 + k];
        g_lp[idx] = pos[b * (OBS * 4) + (OBS - 1) * 4 + k];
    }
}

// ---------------- combine: h = h_se + h_pe into both decoder slots ----------------
__global__ void combine_state() {
    int i = blockIdx.x * blockDim.x + threadIdx.x;
    if (i >= BATCH * H) return;
    float hs = g_h[0][i] + g_h[1][i];
    float cs = g_c[0][i] + g_c[1][i];
    g_h[0][i] = hs; g_h[1][i] = hs;
    g_c[0][i] = cs; g_c[1][i] = cs;
    __nv_bfloat16 hi = __float2bfloat16(hs);
    __nv_bfloat16 lo = __float2bfloat16(hs - __bfloat162float(hi));
    g_hhi[0][0][i] = hi; g_hhi[1][0][i] = hi;
    g_hlo[0][0][i] = lo; g_hlo[1][0][i] = lo;
}

// ---------------- fused LSTM cell: split-bf16 GEMM (mma.sync) + pointwise ----------------
__global__ void __launch_bounds__(256) lstm_cell(
    int lstm_base, const float* x0, const float* x1, int xstride,
    int internal_x, int rp)
{
    extern __shared__ char smem[];
    __shared__ float sWi[128 * 4];
    __shared__ float sB[128];

    const int z = blockIdx.z;
    const int lstm = lstm_base + z;
    const int slot = z;
    const int wp = 1 - rp;
    const int m0 = blockIdx.y * BM;
    const int n0 = blockIdx.x * BN;
    const int tid = threadIdx.x;
    const int lane = tid & 31;
    const int warp = tid >> 5;
    const int wm = warp & 3;     // 4 m-blocks of 32
    const int wn = warp >> 2;    // 2 n-blocks of 64

    const float* x = internal_x ? (z ? g_lp : g_ls) : (z ? x1 : x0);
    const __nv_bfloat16* hhi = g_hhi[slot][rp];
    const __nv_bfloat16* hlo = g_hlo[slot][rp];
    const __nv_bfloat16* Wsp = g_Ws[lstm];

    if (tid < 128) {
        int n = n0 + tid;
        sB[tid] = g_bb[lstm][n];
        #pragma unroll
        for (int k = 0; k < 4; k++) sWi[tid * 4 + k] = g_Wi[lstm][n * 4 + k];
    }

    __nv_bfloat16* As = (__nv_bfloat16*)smem;                       // 2 bufs [128][LDT]
    __nv_bfloat16* Bs = (__nv_bfloat16*)(smem + 2 * TILE_BYTES);    // 2 bufs [128][LDT]
    float* Gs = (float*)smem;                                       // reused after mainloop

    float acc[2][8][4] = {};

    auto load_chunk = [&](int kc, int buf) {
        int kg = kc * BK;
        const __nv_bfloat16* asrc; int ac;
        if (kg < 512)       { asrc = hhi; ac = kg; }
        else if (kg < 1024) { asrc = hhi; ac = kg - 512; }
        else                { asrc = hlo; ac = kg - 1024; }
        int bc = (kg < 1024) ? kg : (kg - 1024);
        #pragma unroll
        for (int r = 0; r < 2; r++) {
            int idx = tid + r * 256;
            int row = idx >> 2, seg = idx & 3;
            cp16(su32(As + buf * TILE_ELEMS + row * LDT + seg * 8),
                 asrc + (size_t)(m0 + row) * H + ac + seg * 8);
            cp16(su32(Bs + buf * TILE_ELEMS + row * LDT + seg * 8),
                 Wsp + (size_t)(n0 + row) * 1024 + bc + seg * 8);
        }
    };

    load_chunk(0, 0);
    asm volatile("cp.async.commit_group;");

    for (int kc = 0; kc < NCHUNK; kc++) {
        int buf = kc & 1;
        if (kc + 1 < NCHUNK) load_chunk(kc + 1, buf ^ 1);
        asm volatile("cp.async.commit_group;");
        asm volatile("cp.async.wait_group 1;");
        __syncthreads();

        const __nv_bfloat16* Ab = As + buf * TILE_ELEMS;
        const __nv_bfloat16* Bb = Bs + buf * TILE_ELEMS;
        #pragma unroll
        for (int kk = 0; kk < BK; kk += 16) {
            uint32_t a[2][4];
            #pragma unroll
            for (int im = 0; im < 2; im++) {
                int row = wm * 32 + im * 16 + (lane & 15);
                int col = kk + ((lane >> 4) << 3);
                unsigned ad = su32(Ab + row * LDT + col);
                asm volatile("ldmatrix.sync.aligned.m8n8.x4.shared.b16 {%0,%1,%2,%3}, [%4];"
                    : "=r"(a[im][0]), "=r"(a[im][1]), "=r"(a[im][2]), "=r"(a[im][3]) : "r"(ad));
            }
            uint32_t bfr[8][2];
            #pragma unroll
            for (int gp = 0; gp < 4; gp++) {
                int idx = lane & 7;
                int half = (lane >> 3) & 1;
                int grp = lane >> 4;
                int row = wn * 64 + gp * 16 + grp * 8 + idx;
                int col = kk + half * 8;
                unsigned bd = su32(Bb + row * LDT + col);
                asm volatile("ldmatrix.sync.aligned.m8n8.x4.shared.b16 {%0,%1,%2,%3}, [%4];"
                    : "=r"(bfr[2 * gp][0]), "=r"(bfr[2 * gp][1]),
                      "=r"(bfr[2 * gp + 1][0]), "=r"(bfr[2 * gp + 1][1]) : "r"(bd));
            }
            #pragma unroll
            for (int im = 0; im < 2; im++)
                #pragma unroll
                for (int g = 0; g < 8; g++)
                    asm volatile("mma.sync.aligned.m16n8k16.row.col.f32.bf16.bf16.f32 "
                        "{%0,%1,%2,%3}, {%4,%5,%6,%7}, {%8,%9}, {%0,%1,%2,%3};"
                        : "+f"(acc[im][g][0]), "+f"(acc[im][g][1]),
                          "+f"(acc[im][g][2]), "+f"(acc[im][g][3])
                        : "r"(a[im][0]), "r"(a[im][1]), "r"(a[im][2]), "r"(a[im][3]),
                          "r"(bfr[g][0]), "r"(bfr[g][1]));
        }
        __syncthreads();
    }

    // stage fp32 gates to smem for gate-group transpose
    #pragma unroll
    for (int im = 0; im < 2; im++)
        #pragma unroll
        for (int g = 0; g < 8; g++) {
            int r = wm * 32 + im * 16 + (lane >> 2);
            int c = wn * 64 + g * 8 + 2 * (lane & 3);
            Gs[r * 132 + c]           = acc[im][g][0];
            Gs[r * 132 + c + 1]       = acc[im][g][1];
            Gs[(r + 8) * 132 + c]     = acc[im][g][2];
            Gs[(r + 8) * 132 + c + 1] = acc[im][g][3];
        }
    __syncthreads();

    float* hout = g_h[slot];
    float* cio  = g_c[slot];
    __nv_bfloat16* hhiw = g_hhi[slot][wp];
    __nv_bfloat16* hlow = g_hlo[slot][wp];

    for (int i = 0; i < 16; i++) {
        int p = tid + 256 * i;
        int m = p >> 5, ul = p & 31;
        int mg = m0 + m;
        int ug = (n0 >> 2) + ul;
        const float4 gv = *(const float4*)&Gs[m * 132 + 4 * ul];
        const float* xr = x + (size_t)mg * xstride;
        float xv0 = xr[0], xv1 = xr[1], xv2 = xr[2], xv3 = xr[3];
        float gate[4] = { gv.x, gv.y, gv.z, gv.w };
        #pragma unroll
        for (int j = 0; j < 4; j++) {
            int nn = 4 * ul + j;
            gate[j] += sB[nn] + xv0 * sWi[nn * 4 + 0] + xv1 * sWi[nn * 4 + 1]
                              + xv2 * sWi[nn * 4 + 2] + xv3 * sWi[nn * 4 + 3];
        }
        float iv = sigf(gate[0]);
        float fv = sigf(gate[1]);
        float gg = tanhfast(gate[2]);
        float ov = sigf(gate[3]);
        size_t ci = (size_t)mg * H + ug;
        float cn = fv * cio[ci] + iv * gg;
        float hn = ov * tanhfast(cn);
        cio[ci] = cn;
        hout[ci] = hn;
        __nv_bfloat16 hib = __float2bfloat16(hn);
        hhiw[ci] = hib;
        hlow[ci] = __float2bfloat16(hn - __bfloat162float(hib));
    }
}

// ---------------- decoder projections + feedback ----------------
__global__ void proj_kernel(const float* W_fs, const float* b_fs,
                            const float* W_fc, const float* b_fc,
                            const float* W_emb, const float* b_emb,
                            float* out, int t)
{
    int warp = threadIdx.x >> 5, lane = threadIdx.x & 31;
    int b = blockIdx.x * 8 + warp;
    float a0 = 0, a1 = 0, a2 = 0, a3 = 0, a4 = 0, a5 = 0;
    const float* hs = g_h[0] + (size_t)b * H;
    const float* hi = g_h[1] + (size_t)b * H;
    for (int k = lane; k < H; k += 32) {
        float vs = hs[k], vi = hi[k];
        a0 += vs * W_fs[k];
        a1 += vs * W_fs[H + k];
        a2 += vs * W_fs[2 * H + k];
        a3 += vs * W_fs[3 * H + k];
        a4 += vi * W_fc[k];
        a5 += vi * W_fc[H + k];
    }
    #pragma unroll
    for (int o = 16; o; o >>= 1) {
        a0 += __shfl_down_sync(0xffffffffu, a0, o);
        a1 += __shfl_down_sync(0xffffffffu, a1, o);
        a2 += __shfl_down_sync(0xffffffffu, a2, o);
        a3 += __shfl_down_sync(0xffffffffu, a3, o);
        a4 += __shfl_down_sync(0xffffffffu, a4, o);
        a5 += __shfl_down_sync(0xffffffffu, a5, o);
    }
    if (lane == 0) {
        float4 spv;
        spv.x = fminf(fmaxf(a0 + b_fs[0], -100.f), 100.f);
        spv.y = fminf(fmaxf(a1 + b_fs[1], -100.f), 100.f);
        spv.z = fminf(fmaxf(a2 + b_fs[2], -100.f), 100.f);
        spv.w = fminf(fmaxf(a3 + b_fs[3], -100.f), 100.f);
        float it0 = fmaxf(a4 + b_fc[0], 0.f);
        float it1 = fmaxf(a5 + b_fc[1], 0.f);
        *(float4*)&out[((size_t)b * TDEC + t) * 4] = spv;
        *(float4*)&g_ls[b * 4] = spv;
        float4 lpv;
        lpv.x = fmaxf(W_emb[0] * it0 + W_emb[1] * it1 + b_emb[0], 0.f);
        lpv.y = fmaxf(W_emb[2] * it0 + W_emb[3] * it1 + b_emb[1], 0.f);
        lpv.z = fmaxf(W_emb[4] * it0 + W_emb[5] * it1 + b_emb[2], 0.f);
        lpv.w = fmaxf(W_emb[6] * it0 + W_emb[7] * it1 + b_emb[3], 0.f);
        *(float4*)&g_lp[b * 4] = lpv;
        if (t == TDEC - 1) {
            float mx = fmaxf(it0, it1);
            float e0 = expf(it0 - mx), e1 = expf(it1 - mx);
            float s = e0 + e1;
            out[(size_t)BATCH * TDEC * 4 + b * 2]     = e0 / s;
            out[(size_t)BATCH * TDEC * 4 + b * 2 + 1] = e1 / s;
        }
    }
}

// ---------------- launch ----------------
extern "C" void kernel_launch(void* const* d_in, const int* in_sizes, int n_in,
                              void* d_out, int out_size)
{
    const float* speed = (const float*)d_in[0];
    const float* pos   = (const float*)d_in[1];
    WPtrs wpt;
    wpt.Wi[0] = (const float*)d_in[2];  wpt.Wh[0] = (const float*)d_in[3];  wpt.bb[0] = (const float*)d_in[4];
    wpt.Wi[1] = (const float*)d_in[5];  wpt.Wh[1] = (const float*)d_in[6];  wpt.bb[1] = (const float*)d_in[7];
    wpt.Wi[2] = (const float*)d_in[8];  wpt.Wh[2] = (const float*)d_in[9];  wpt.bb[2] = (const float*)d_in[10];
    wpt.Wi[3] = (const float*)d_in[11]; wpt.Wh[3] = (const float*)d_in[12]; wpt.bb[3] = (const float*)d_in[13];
    const float* W_fs  = (const float*)d_in[14];
    const float* b_fs  = (const float*)d_in[15];
    const float* W_fc  = (const float*)d_in[16];
    const float* b_fc  = (const float*)d_in[17];
    const float* W_emb = (const float*)d_in[18];
    const float* b_emb = (const float*)d_in[19];
    float* out = (float*)d_out;

    cudaFuncSetAttribute(lstm_cell, cudaFuncAttributeMaxDynamicSharedMemorySize, DYN_SMEM);

    prep_weights<<<dim3(NG, 4), 512>>>(wpt);
    init_state<<<(2 * BATCH * H + 255) / 256, 256>>>(speed, pos);

    dim3 cgrid(NG / BN, BATCH / BM, 2);   // (16, 32, 2)
    for (int t = 0; t < OBS; t++)
        lstm_cell<<<cgrid, 256, DYN_SMEM>>>(0, speed + t * 4, pos + t * 4, OBS * 4, 0, t & 1);

    combine_state<<<(BATCH * H + 255) / 256, 256>>>();

    for (int t = 0; t < TDEC; t++) {
        lstm_cell<<<cgrid, 256, DYN_SMEM>>>(2, nullptr, nullptr, 4, 1, t & 1);
        proj_kernel<<<BATCH / 8, 256>>>(W_fs, b_fs, W_fc, b_fc, W_emb, b_emb, out, t);
    }
}

// round 2
// speedup vs baseline: 1.0314x; 1.0314x over previous
#include <cuda_runtime.h>
#include <cuda_bf16.h>
#include <cstdint>

#define BATCH 4096
#define OBS 16
#define TDEC 32
#define H 512
#define NG 2048          // 4*H gate columns
#define KTOT 1536        // split-K: [h_hi | h_hi | h_lo]
#define BM 128
#define BN 128
#define BK 32
#define NCHUNK (KTOT / BK)   // 48
#define LDT 40               // padded smem row length (bf16 elems) -> 80B stride, conflict-free
#define TILE_ELEMS (128 * LDT)
#define TILE_BYTES (TILE_ELEMS * 2)      // 10240
#define DYN_SMEM 67584                   // 128 * 132 * 4 for fp32 gate staging (union w/ tiles)

// ---------------- device state (no cudaMalloc allowed) ----------------
__device__ __align__(16) float          g_h[2][BATCH * H];
__device__ __align__(16) float          g_c[2][BATCH * H];
__device__ __align__(16) __nv_bfloat16  g_hhi[2][2][BATCH * H];   // [slot][parity]
__device__ __align__(16) __nv_bfloat16  g_hlo[2][2][BATCH * H];
__device__ __align__(16) __nv_bfloat16  g_Ws[4][NG * 1024];       // [lstm][(4u+gate)*1024 + k] cols: [0,512)=hi, [512,1024)=lo
__device__ __align__(16) float          g_Wi[4][NG * 4];          // permuted
__device__ __align__(16) float          g_bb[4][NG];              // permuted
__device__ __align__(16) float          g_ls[BATCH * 4];
__device__ __align__(16) float          g_lp[BATCH * 4];

// ---------------- helpers ----------------
__device__ __forceinline__ unsigned su32(const void* p) {
    return (unsigned)__cvta_generic_to_shared(p);
}
__device__ __forceinline__ void cp16(unsigned d, const void* s) {
    asm volatile("cp.async.cg.shared.global [%0], [%1], 16;" :: "r"(d), "l"(s));
}
__device__ __forceinline__ float sigf(float x) { return 1.f / (1.f + __expf(-x)); }
__device__ __forceinline__ float tanhfast(float x) { return 2.f / (1.f + __expf(-2.f * x)) - 1.f; }

// ---------------- weight prep: split to bf16 hi/lo + gate-interleave permute ----------------
struct WPtrs { const float* Wh[4]; const float* Wi[4]; const float* bb[4]; };

__global__ void prep_weights(WPtrs p) {
    int k = threadIdx.x;        // 0..511
    int j = blockIdx.x;         // 0..2047 original gate row
    int l = blockIdx.y;         // 0..3 lstm id
    float w = p.Wh[l][j * H + k];
    __nv_bfloat16 hi = __float2bfloat16(w);
    __nv_bfloat16 lo = __float2bfloat16(w - __bfloat162float(hi));
    int pr = 4 * (j & (H - 1)) + (j >> 9);   // 4u + gate
    g_Ws[l][pr * 1024 + k] = hi;
    g_Ws[l][pr * 1024 + 512 + k] = lo;
    if (k < 4)  g_Wi[l][pr * 4 + k] = p.Wi[l][j * 4 + k];
    if (k == 0) g_bb[l][pr] = p.bb[l][j];
}

// ---------------- init: zero states, seed feedback with last observation ----------------
__global__ void init_state(const float* speed, const float* pos) {
    int idx = blockIdx.x * blockDim.x + threadIdx.x;
    if (idx < 2 * BATCH * H) {
        int s = idx / (BATCH * H);
        int i = idx % (BATCH * H);
        g_h[s][i] = 0.f;
        g_c[s][i] = 0.f;
        g_hhi[s][0][i] = __float2bfloat16(0.f);
        g_hlo[s][0][i] = __float2bfloat16(0.f);
    }
    if (idx < BATCH * 4) {
        int b = idx >> 2, k = idx & 3;
        g_ls[idx] = speed[b * (OBS * 4) + (OBS - 1) * 4 + k];
        g_lp[idx] = pos[b * (OBS * 4) + (OBS - 1) * 4 + k];
    }
}

// ---------------- combine: h = h_se + h_pe into both decoder slots ----------------
__global__ void combine_state() {
    int i = blockIdx.x * blockDim.x + threadIdx.x;
    if (i >= BATCH * H) return;
    float hs = g_h[0][i] + g_h[1][i];
    float cs = g_c[0][i] + g_c[1][i];
    g_h[0][i] = hs; g_h[1][i] = hs;
    g_c[0][i] = cs; g_c[1][i] = cs;
    __nv_bfloat16 hi = __float2bfloat16(hs);
    __nv_bfloat16 lo = __float2bfloat16(hs - __bfloat162float(hi));
    g_hhi[0][0][i] = hi; g_hhi[1][0][i] = hi;
    g_hlo[0][0][i] = lo; g_hlo[1][0][i] = lo;
}

// ---------------- fused LSTM cell: split-bf16 GEMM (mma.sync) + pointwise ----------------
__global__ void __launch_bounds__(256) lstm_cell(
    int lstm_base, const float* x0, const float* x1, int xstride,
    int internal_x, int rp)
{
    extern __shared__ char smem[];
    __shared__ float sWi[128 * 4];
    __shared__ float sB[128];

    const int z = blockIdx.z;
    const int lstm = lstm_base + z;
    const int slot = z;
    const int wp = 1 - rp;
    const int m0 = blockIdx.y * BM;
    const int n0 = blockIdx.x * BN;
    const int tid = threadIdx.x;
    const int lane = tid & 31;
    const int warp = tid >> 5;
    const int wm = warp & 3;     // 4 m-blocks of 32
    const int wn = warp >> 2;    // 2 n-blocks of 64

    const float* x = internal_x ? (z ? g_lp : g_ls) : (z ? x1 : x0);
    const __nv_bfloat16* hhi = g_hhi[slot][rp];
    const __nv_bfloat16* hlo = g_hlo[slot][rp];
    const __nv_bfloat16* Wsp = g_Ws[lstm];

    if (tid < 128) {
        int n = n0 + tid;
        sB[tid] = g_bb[lstm][n];
        #pragma unroll
        for (int k = 0; k < 4; k++) sWi[tid * 4 + k] = g_Wi[lstm][n * 4 + k];
    }

    __nv_bfloat16* As = (__nv_bfloat16*)smem;                       // 2 bufs [128][LDT]
    __nv_bfloat16* Bs = (__nv_bfloat16*)(smem + 2 * TILE_BYTES);    // 2 bufs [128][LDT]
    float* Gs = (float*)smem;                                       // reused after mainloop

    float acc[2][8][4] = {};

    auto load_chunk = [&](int kc, int buf) {
        int kg = kc * BK;
        const __nv_bfloat16* asrc; int ac;
        if (kg < 512)       { asrc = hhi; ac = kg; }
        else if (kg < 1024) { asrc = hhi; ac = kg - 512; }
        else                { asrc = hlo; ac = kg - 1024; }
        int bc = (kg < 1024) ? kg : (kg - 1024);
        #pragma unroll
        for (int r = 0; r < 2; r++) {
            int idx = tid + r * 256;
            int row = idx >> 2, seg = idx & 3;
            cp16(su32(As + buf * TILE_ELEMS + row * LDT + seg * 8),
                 asrc + (size_t)(m0 + row) * H + ac + seg * 8);
            cp16(su32(Bs + buf * TILE_ELEMS + row * LDT + seg * 8),
                 Wsp + (size_t)(n0 + row) * 1024 + bc + seg * 8);
        }
    };

    load_chunk(0, 0);
    asm volatile("cp.async.commit_group;");

    for (int kc = 0; kc < NCHUNK; kc++) {
        int buf = kc & 1;
        if (kc + 1 < NCHUNK) load_chunk(kc + 1, buf ^ 1);
        asm volatile("cp.async.commit_group;");
        asm volatile("cp.async.wait_group 1;");
        __syncthreads();

        const __nv_bfloat16* Ab = As + buf * TILE_ELEMS;
        const __nv_bfloat16* Bb = Bs + buf * TILE_ELEMS;
        #pragma unroll
        for (int kk = 0; kk < BK; kk += 16) {
            uint32_t a[2][4];
            #pragma unroll
            for (int im = 0; im < 2; im++) {
                int row = wm * 32 + im * 16 + (lane & 15);
                int col = kk + ((lane >> 4) << 3);
                unsigned ad = su32(Ab + row * LDT + col);
                asm volatile("ldmatrix.sync.aligned.m8n8.x4.shared.b16 {%0,%1,%2,%3}, [%4];"
                    : "=r"(a[im][0]), "=r"(a[im][1]), "=r"(a[im][2]), "=r"(a[im][3]) : "r"(ad));
            }
            uint32_t bfr[8][2];
            #pragma unroll
            for (int gp = 0; gp < 4; gp++) {
                int idx = lane & 7;
                int half = (lane >> 3) & 1;
                int grp = lane >> 4;
                int row = wn * 64 + gp * 16 + grp * 8 + idx;
                int col = kk + half * 8;
                unsigned bd = su32(Bb + row * LDT + col);
                asm volatile("ldmatrix.sync.aligned.m8n8.x4.shared.b16 {%0,%1,%2,%3}, [%4];"
                    : "=r"(bfr[2 * gp][0]), "=r"(bfr[2 * gp][1]),
                      "=r"(bfr[2 * gp + 1][0]), "=r"(bfr[2 * gp + 1][1]) : "r"(bd));
            }
            #pragma unroll
            for (int im = 0; im < 2; im++)
                #pragma unroll
                for (int g = 0; g < 8; g++)
                    asm volatile("mma.sync.aligned.m16n8k16.row.col.f32.bf16.bf16.f32 "
                        "{%0,%1,%2,%3}, {%4,%5,%6,%7}, {%8,%9}, {%0,%1,%2,%3};"
                        : "+f"(acc[im][g][0]), "+f"(acc[im][g][1]),
                          "+f"(acc[im][g][2]), "+f"(acc[im][g][3])
                        : "r"(a[im][0]), "r"(a[im][1]), "r"(a[im][2]), "r"(a[im][3]),
                          "r"(bfr[g][0]), "r"(bfr[g][1]));
        }
        __syncthreads();
    }

    // stage fp32 gates to smem for gate-group transpose
    #pragma unroll
    for (int im = 0; im < 2; im++)
        #pragma unroll
        for (int g = 0; g < 8; g++) {
            int r = wm * 32 + im * 16 + (lane >> 2);
            int c = wn * 64 + g * 8 + 2 * (lane & 3);
            Gs[r * 132 + c]           = acc[im][g][0];
            Gs[r * 132 + c + 1]       = acc[im][g][1];
            Gs[(r + 8) * 132 + c]     = acc[im][g][2];
            Gs[(r + 8) * 132 + c + 1] = acc[im][g][3];
        }
    __syncthreads();

    float* hout = g_h[slot];
    float* cio  = g_c[slot];
    __nv_bfloat16* hhiw = g_hhi[slot][wp];
    __nv_bfloat16* hlow = g_hlo[slot][wp];

    for (int i = 0; i < 16; i++) {
        int p = tid + 256 * i;
        int m = p >> 5, ul = p & 31;
        int mg = m0 + m;
        int ug = (n0 >> 2) + ul;
        const float4 gv = *(const float4*)&Gs[m * 132 + 4 * ul];
        const float* xr = x + (size_t)mg * xstride;
        float xv0 = xr[0], xv1 = xr[1], xv2 = xr[2], xv3 = xr[3];
        float gate[4] = { gv.x, gv.y, gv.z, gv.w };
        #pragma unroll
        for (int j = 0; j < 4; j++) {
            int nn = 4 * ul + j;
            gate[j] += sB[nn] + xv0 * sWi[nn * 4 + 0] + xv1 * sWi[nn * 4 + 1]
                              + xv2 * sWi[nn * 4 + 2] + xv3 * sWi[nn * 4 + 3];
        }
        float iv = sigf(gate[0]);
        float fv = sigf(gate[1]);
        float gg = tanhfast(gate[2]);
        float ov = sigf(gate[3]);
        size_t ci = (size_t)mg * H + ug;
        float cn = fv * cio[ci] + iv * gg;
        float hn = ov * tanhfast(cn);
        cio[ci] = cn;
        hout[ci] = hn;
        __nv_bfloat16 hib = __float2bfloat16(hn);
        hhiw[ci] = hib;
        hlow[ci] = __float2bfloat16(hn - __bfloat162float(hib));
    }
}

// ---------------- decoder projections + feedback ----------------
__global__ void proj_kernel(const float* W_fs, const float* b_fs,
                            const float* W_fc, const float* b_fc,
                            const float* W_emb, const float* b_emb,
                            float* out, int t)
{
    int warp = threadIdx.x >> 5, lane = threadIdx.x & 31;
    int b = blockIdx.x * 8 + warp;
    float a0 = 0, a1 = 0, a2 = 0, a3 = 0, a4 = 0, a5 = 0;
    const float* hs = g_h[0] + (size_t)b * H;
    const float* hi = g_h[1] + (size_t)b * H;
    for (int k = lane; k < H; k += 32) {
        float vs = hs[k], vi = hi[k];
        a0 += vs * W_fs[k];
        a1 += vs * W_fs[H + k];
        a2 += vs * W_fs[2 * H + k];
        a3 += vs * W_fs[3 * H + k];
        a4 += vi * W_fc[k];
        a5 += vi * W_fc[H + k];
    }
    #pragma unroll
    for (int o = 16; o; o >>= 1) {
        a0 += __shfl_down_sync(0xffffffffu, a0, o);
        a1 += __shfl_down_sync(0xffffffffu, a1, o);
        a2 += __shfl_down_sync(0xffffffffu, a2, o);
        a3 += __shfl_down_sync(0xffffffffu, a3, o);
        a4 += __shfl_down_sync(0xffffffffu, a4, o);
        a5 += __shfl_down_sync(0xffffffffu, a5, o);
    }
    if (lane == 0) {
        float4 spv;
        spv.x = fminf(fmaxf(a0 + b_fs[0], -100.f), 100.f);
        spv.y = fminf(fmaxf(a1 + b_fs[1], -100.f), 100.f);
        spv.z = fminf(fmaxf(a2 + b_fs[2], -100.f), 100.f);
        spv.w = fminf(fmaxf(a3 + b_fs[3], -100.f), 100.f);
        float it0 = fmaxf(a4 + b_fc[0], 0.f);
        float it1 = fmaxf(a5 + b_fc[1], 0.f);
        *(float4*)&out[((size_t)b * TDEC + t) * 4] = spv;
        *(float4*)&g_ls[b * 4] = spv;
        float4 lpv;
        lpv.x = fmaxf(W_emb[0] * it0 + W_emb[1] * it1 + b_emb[0], 0.f);
        lpv.y = fmaxf(W_emb[2] * it0 + W_emb[3] * it1 + b_emb[1], 0.f);
        lpv.z = fmaxf(W_emb[4] * it0 + W_emb[5] * it1 + b_emb[2], 0.f);
        lpv.w = fmaxf(W_emb[6] * it0 + W_emb[7] * it1 + b_emb[3], 0.f);
        *(float4*)&g_lp[b * 4] = lpv;
        if (t == TDEC - 1) {
            float mx = fmaxf(it0, it1);
            float e0 = expf(it0 - mx), e1 = expf(it1 - mx);
            float s = e0 + e1;
            out[(size_t)BATCH * TDEC * 4 + b * 2]     = e0 / s;
            out[(size_t)BATCH * TDEC * 4 + b * 2 + 1] = e1 / s;
        }
    }
}

// ---------------- launch ----------------
extern "C" void kernel_launch(void* const* d_in, const int* in_sizes, int n_in,
                              void* d_out, int out_size)
{
    const float* speed = (const float*)d_in[0];
    const float* pos   = (const float*)d_in[1];
    WPtrs wpt;
    wpt.Wi[0] = (const float*)d_in[2];  wpt.Wh[0] = (const float*)d_in[3];  wpt.bb[0] = (const float*)d_in[4];
    wpt.Wi[1] = (const float*)d_in[5];  wpt.Wh[1] = (const float*)d_in[6];  wpt.bb[1] = (const float*)d_in[7];
    wpt.Wi[2] = (const float*)d_in[8];  wpt.Wh[2] = (const float*)d_in[9];  wpt.bb[2] = (const float*)d_in[10];
    wpt.Wi[3] = (const float*)d_in[11]; wpt.Wh[3] = (const float*)d_in[12]; wpt.bb[3] = (const float*)d_in[13];
    const float* W_fs  = (const float*)d_in[14];
    const float* b_fs  = (const float*)d_in[15];
    const float* W_fc  = (const float*)d_in[16];
    const float* b_fc  = (const float*)d_in[17];
    const float* W_emb = (const float*)d_in[18];
    const float* b_emb = (const float*)d_in[19];
    float* out = (float*)d_out;

    cudaFuncSetAttribute(lstm_cell, cudaFuncAttributeMaxDynamicSharedMemorySize, DYN_SMEM);

    prep_weights<<<dim3(NG, 4), 512>>>(wpt);
    init_state<<<(2 * BATCH * H + 255) / 256, 256>>>(speed, pos);

    dim3 cgrid(NG / BN, BATCH / BM, 2);   // (16, 32, 2)
    for (int t = 0; t < OBS; t++)
        lstm_cell<<<cgrid, 256, DYN_SMEM>>>(0, speed + t * 4, pos + t * 4, OBS * 4, 0, t & 1);

    combine_state<<<(BATCH * H + 255) / 256, 256>>>();

    for (int t = 0; t < TDEC; t++) {
        lstm_cell<<<cgrid, 256, DYN_SMEM>>>(2, nullptr, nullptr, 4, 1, t & 1);
        proj_kernel<<<BATCH / 8, 256>>>(W_fs, b_fs, W_fc, b_fc, W_emb, b_emb, out, t);
    }
}

// round 6
// speedup vs baseline: 1.4767x; 1.4318x over previous
#include <cuda_runtime.h>
#include <cuda_fp16.h>
#include <cstdint>

#define BATCH 4096
#define OBS 16
#define TDEC 32
#define H 512
#define NG 2048
#define KTOT 1024            // [h_hi | h_lo] x [W | W]  (fp16)
#define KC 64
#define NSTAGE 16            // 1024/64
#define DEPTH 3
#define BM 128
#define BN 128
#define THREADS 128
#define STAGE_BYTES 32768    // A 16K | B 16K
#define DYN_SMEM (DEPTH * STAGE_BYTES)   // 98304 (Gs 67584 fits)

// ---------------- device state ----------------
__device__ __align__(16) float   g_h[2][BATCH * H];        // row-major [m][u]
__device__ __align__(16) float   g_c[2][BATCH * H];
__device__ __align__(16) __half  g_hhi[2][2][BATCH * H];   // [slot][parity]
__device__ __align__(16) __half  g_hlo[2][2][BATCH * H];
__device__ __align__(16) __half  g_Ws[4][NG * 512];        // [(4u+g)][k] fp16
__device__ __align__(16) float   g_Wi[4][NG * 4];
__device__ __align__(16) float   g_bb[4][NG];
__device__ __align__(16) float   g_ls[BATCH * 4];
__device__ __align__(16) float   g_lp[BATCH * 4];

// ---------------- helpers ----------------
__device__ __forceinline__ unsigned su32(const void* p) {
    return (unsigned)__cvta_generic_to_shared(p);
}
__device__ __forceinline__ void cp16(unsigned d, const void* s) {
    asm volatile("cp.async.cg.shared.global [%0], [%1], 16;" :: "r"(d), "l"(s));
}
__device__ __forceinline__ unsigned swz(unsigned o) { return o ^ ((o >> 3) & 0x70); }
__device__ __forceinline__ float sigf(float x) { return 1.f / (1.f + __expf(-x)); }
__device__ __forceinline__ float tanhfast(float x) { return 2.f / (1.f + __expf(-2.f * x)) - 1.f; }

// ---------------- weight prep ----------------
struct WPtrs { const float* Wh[4]; const float* Wi[4]; const float* bb[4]; };

__global__ void prep_weights(WPtrs p) {
    int k = threadIdx.x, j = blockIdx.x, l = blockIdx.y;
    float w = p.Wh[l][j * H + k];
    int pr = 4 * (j & (H - 1)) + (j >> 9);   // 4u + gate
    g_Ws[l][pr * 512 + k] = __float2half(w);
    if (k < 4)  g_Wi[l][pr * 4 + k] = p.Wi[l][j * 4 + k];
    if (k == 0) g_bb[l][pr] = p.bb[l][j];
}

__global__ void init_state(const float* speed, const float* pos) {
    int idx = blockIdx.x * blockDim.x + threadIdx.x;
    if (idx < 2 * BATCH * H) {
        int s = idx / (BATCH * H), i = idx % (BATCH * H);
        g_h[s][i] = 0.f; g_c[s][i] = 0.f;
        g_hhi[s][0][i] = __float2half(0.f);
        g_hlo[s][0][i] = __float2half(0.f);
    }
    if (idx < BATCH * 4) {
        int b = idx >> 2, k = idx & 3;
        g_ls[idx] = speed[b * (OBS * 4) + (OBS - 1) * 4 + k];
        g_lp[idx] = pos[b * (OBS * 4) + (OBS - 1) * 4 + k];
    }
}

__global__ void combine_state() {
    int i = blockIdx.x * blockDim.x + threadIdx.x;
    float hs = g_h[0][i] + g_h[1][i];
    float cs = g_c[0][i] + g_c[1][i];
    g_h[0][i] = hs; g_h[1][i] = hs;
    g_c[0][i] = cs; g_c[1][i] = cs;
    __half hi = __float2half(hs);
    __half lo = __float2half(hs - __half2float(hi));
    g_hhi[0][0][i] = hi; g_hhi[1][0][i] = hi;
    g_hlo[0][0][i] = lo; g_hlo[1][0][i] = lo;
}

// ---------------- fused LSTM cell: fp16 mma.sync, 128x128 tile, 64x64 warp tile ----------------
__global__ void __launch_bounds__(THREADS, 2) lstm_cell(
    int lstm_base, const float* x0, const float* x1, int xstride, int internal_x, int rp)
{
    extern __shared__ char smem[];
    __shared__ float sB[BN];
    __shared__ float sWi[BN * 4];

    const int z = blockIdx.z;
    const int lstm = lstm_base + z;
    const int slot = z;
    const int wp = 1 - rp;
    const int n0 = blockIdx.x * BN;
    const int m0 = blockIdx.y * BM;
    const int tid = threadIdx.x;
    const int lane = tid & 31, warp = tid >> 5;
    const int wmb = (warp & 1) * 64;   // warp m base
    const int wnb = (warp >> 1) * 64;  // warp n base

    const float* x = internal_x ? (z ? g_lp : g_ls) : (z ? x1 : x0);
    const __half* hhi = g_hhi[slot][rp];
    const __half* hlo = g_hlo[slot][rp];
    const __half* Wsp = g_Ws[lstm];

    {
        int n = n0 + tid;
        sB[tid] = g_bb[lstm][n];
        #pragma unroll
        for (int k = 0; k < 4; k++) sWi[tid * 4 + k] = g_Wi[lstm][n * 4 + k];
    }

    float acc[4][8][4] = {};

    auto produce = [&](int sp) {
        int kg = sp * KC;
        const __half* asrc = (kg < 512) ? hhi : hlo;
        int kc = kg & 511;
        unsigned sbase = (unsigned)((sp % DEPTH) * STAGE_BYTES);
        #pragma unroll
        for (int r = 0; r < 8; r++) {
            int idx = tid + r * THREADS;
            int row = idx >> 3, seg = idx & 7;
            cp16(su32(smem + sbase + swz(row * 128 + seg * 16)),
                 asrc + (size_t)(m0 + row) * 512 + kc + seg * 8);
        }
        #pragma unroll
        for (int r = 0; r < 8; r++) {
            int idx = tid + r * THREADS;
            int row = idx >> 3, seg = idx & 7;
            cp16(su32(smem + sbase + 16384 + swz(row * 128 + seg * 16)),
                 Wsp + (size_t)(n0 + row) * 512 + kc + seg * 8);
        }
        asm volatile("cp.async.commit_group;");
    };

    produce(0);
    produce(1);

    for (int s = 0; s < NSTAGE; s++) {
        if (s == NSTAGE - 1) asm volatile("cp.async.wait_group 0;");
        else                 asm volatile("cp.async.wait_group 1;");
        __syncthreads();
        if (s + 2 < NSTAGE) produce(s + 2);

        const char* Ab = smem + (s % DEPTH) * STAGE_BYTES;
        const char* Bb = Ab + 16384;
        #pragma unroll
        for (int kk = 0; kk < 4; kk++) {           // k16 step within BK=64
            uint32_t a[4][4];
            #pragma unroll
            for (int im = 0; im < 4; im++) {
                int row = wmb + im * 16 + (lane & 15);
                unsigned off = swz(row * 128 + kk * 32 + ((lane >> 4) << 4));
                asm volatile("ldmatrix.sync.aligned.m8n8.x4.shared.b16 {%0,%1,%2,%3}, [%4];"
                    : "=r"(a[im][0]), "=r"(a[im][1]), "=r"(a[im][2]), "=r"(a[im][3])
                    : "r"(su32(Ab + off)));
            }
            uint32_t b[8][2];
            #pragma unroll
            for (int gp = 0; gp < 4; gp++) {
                int row = wnb + gp * 16 + ((lane >> 4) << 3) + (lane & 7);
                unsigned off = swz(row * 128 + kk * 32 + (((lane >> 3) & 1) << 4));
                asm volatile("ldmatrix.sync.aligned.m8n8.x4.shared.b16 {%0,%1,%2,%3}, [%4];"
                    : "=r"(b[2 * gp][0]), "=r"(b[2 * gp][1]),
                      "=r"(b[2 * gp + 1][0]), "=r"(b[2 * gp + 1][1])
                    : "r"(su32(Bb + off)));
            }
            #pragma unroll
            for (int im = 0; im < 4; im++)
                #pragma unroll
                for (int g = 0; g < 8; g++)
                    asm volatile("mma.sync.aligned.m16n8k16.row.col.f32.f16.f16.f32 "
                        "{%0,%1,%2,%3}, {%4,%5,%6,%7}, {%8,%9}, {%0,%1,%2,%3};"
                        : "+f"(acc[im][g][0]), "+f"(acc[im][g][1]),
                          "+f"(acc[im][g][2]), "+f"(acc[im][g][3])
                        : "r"(a[im][0]), "r"(a[im][1]), "r"(a[im][2]), "r"(a[im][3]),
                          "r"(b[g][0]), "r"(b[g][1]));
        }
    }

    // ---------------- epilogue: transpose gates via smem, fused LSTM pointwise ----------------
    float* Gs = (float*)smem;   // [128][132]
    __syncthreads();
    #pragma unroll
    for (int im = 0; im < 4; im++)
        #pragma unroll
        for (int g = 0; g < 8; g++) {
            int r = wmb + im * 16 + (lane >> 2);
            int c = wnb + g * 8 + 2 * (lane & 3);
            Gs[r * 132 + c]           = acc[im][g][0];
            Gs[r * 132 + c + 1]       = acc[im][g][1];
            Gs[(r + 8) * 132 + c]     = acc[im][g][2];
            Gs[(r + 8) * 132 + c + 1] = acc[im][g][3];
        }
    __syncthreads();

    float* hout = g_h[slot];
    float* cio  = g_c[slot];
    __half* hhiw = g_hhi[slot][wp];
    __half* hlow = g_hlo[slot][wp];
    const int u0g = n0 >> 2;

    #pragma unroll 4
    for (int i = 0; i < 32; i++) {
        int p = tid + THREADS * i;
        int m = p >> 5, ul = p & 31;
        int mg = m0 + m;
        const float4 gv = *(const float4*)&Gs[m * 132 + 4 * ul];
        const float* xr = x + (size_t)mg * xstride;
        float xv0 = xr[0], xv1 = xr[1], xv2 = xr[2], xv3 = xr[3];
        float gate[4] = { gv.x, gv.y, gv.z, gv.w };
        #pragma unroll
        for (int j = 0; j < 4; j++) {
            int nn = 4 * ul + j;
            gate[j] += sB[nn] + xv0 * sWi[nn * 4 + 0] + xv1 * sWi[nn * 4 + 1]
                              + xv2 * sWi[nn * 4 + 2] + xv3 * sWi[nn * 4 + 3];
        }
        float iv = sigf(gate[0]);
        float fv = sigf(gate[1]);
        float gg = tanhfast(gate[2]);
        float ov = sigf(gate[3]);
        size_t ci = (size_t)mg * H + u0g + ul;
        float cn = fv * cio[ci] + iv * gg;
        float hn = ov * tanhfast(cn);
        cio[ci] = cn;
        hout[ci] = hn;
        __half hib = __float2half(hn);
        hhiw[ci] = hib;
        hlow[ci] = __float2half(hn - __half2float(hib));
    }
}

// ---------------- decoder projections + feedback ----------------
__global__ void proj_kernel(const float* W_fs, const float* b_fs,
                            const float* W_fc, const float* b_fc,
                            const float* W_emb, const float* b_emb,
                            float* out, int t)
{
    int warp = threadIdx.x >> 5, lane = threadIdx.x & 31;
    int b = blockIdx.x * 8 + warp;
    float a0 = 0, a1 = 0, a2 = 0, a3 = 0, a4 = 0, a5 = 0;
    const float* hs = g_h[0] + (size_t)b * H;
    const float* hi = g_h[1] + (size_t)b * H;
    for (int k = lane; k < H; k += 32) {
        float vs = hs[k], vi = hi[k];
        a0 += vs * W_fs[k];
        a1 += vs * W_fs[H + k];
        a2 += vs * W_fs[2 * H + k];
        a3 += vs * W_fs[3 * H + k];
        a4 += vi * W_fc[k];
        a5 += vi * W_fc[H + k];
    }
    #pragma unroll
    for (int o = 16; o; o >>= 1) {
        a0 += __shfl_down_sync(0xffffffffu, a0, o);
        a1 += __shfl_down_sync(0xffffffffu, a1, o);
        a2 += __shfl_down_sync(0xffffffffu, a2, o);
        a3 += __shfl_down_sync(0xffffffffu, a3, o);
        a4 += __shfl_down_sync(0xffffffffu, a4, o);
        a5 += __shfl_down_sync(0xffffffffu, a5, o);
    }
    if (lane == 0) {
        float4 spv;
        spv.x = fminf(fmaxf(a0 + b_fs[0], -100.f), 100.f);
        spv.y = fminf(fmaxf(a1 + b_fs[1], -100.f), 100.f);
        spv.z = fminf(fmaxf(a2 + b_fs[2], -100.f), 100.f);
        spv.w = fminf(fmaxf(a3 + b_fs[3], -100.f), 100.f);
        float it0 = fmaxf(a4 + b_fc[0], 0.f);
        float it1 = fmaxf(a5 + b_fc[1], 0.f);
        *(float4*)&out[((size_t)b * TDEC + t) * 4] = spv;
        *(float4*)&g_ls[b * 4] = spv;
        float4 lpv;
        lpv.x = fmaxf(W_emb[0] * it0 + W_emb[1] * it1 + b_emb[0], 0.f);
        lpv.y = fmaxf(W_emb[2] * it0 + W_emb[3] * it1 + b_emb[1], 0.f);
        lpv.z = fmaxf(W_emb[4] * it0 + W_emb[5] * it1 + b_emb[2], 0.f);
        lpv.w = fmaxf(W_emb[6] * it0 + W_emb[7] * it1 + b_emb[3], 0.f);
        *(float4*)&g_lp[b * 4] = lpv;
        if (t == TDEC - 1) {
            float mx = fmaxf(it0, it1);
            float e0 = expf(it0 - mx), e1 = expf(it1 - mx);
            float s = e0 + e1;
            out[(size_t)BATCH * TDEC * 4 + b * 2]     = e0 / s;
            out[(size_t)BATCH * TDEC * 4 + b * 2 + 1] = e1 / s;
        }
    }
}

// ---------------- launch ----------------
extern "C" void kernel_launch(void* const* d_in, const int* in_sizes, int n_in,
                              void* d_out, int out_size)
{
    const float* speed = (const float*)d_in[0];
    const float* pos   = (const float*)d_in[1];
    WPtrs wpt;
    wpt.Wi[0] = (const float*)d_in[2];  wpt.Wh[0] = (const float*)d_in[3];  wpt.bb[0] = (const float*)d_in[4];
    wpt.Wi[1] = (const float*)d_in[5];  wpt.Wh[1] = (const float*)d_in[6];  wpt.bb[1] = (const float*)d_in[7];
    wpt.Wi[2] = (const float*)d_in[8];  wpt.Wh[2] = (const float*)d_in[9];  wpt.bb[2] = (const float*)d_in[10];
    wpt.Wi[3] = (const float*)d_in[11]; wpt.Wh[3] = (const float*)d_in[12]; wpt.bb[3] = (const float*)d_in[13];
    const float* W_fs  = (const float*)d_in[14];
    const float* b_fs  = (const float*)d_in[15];
    const float* W_fc  = (const float*)d_in[16];
    const float* b_fc  = (const float*)d_in[17];
    const float* W_emb = (const float*)d_in[18];
    const float* b_emb = (const float*)d_in[19];
    float* out = (float*)d_out;

    cudaFuncSetAttribute(lstm_cell, cudaFuncAttributeMaxDynamicSharedMemorySize, DYN_SMEM);

    prep_weights<<<dim3(NG, 4), 512>>>(wpt);
    init_state<<<(2 * BATCH * H + 255) / 256, 256>>>(speed, pos);

    dim3 cgrid(NG / BN, BATCH / BM, 2);   // (16, 32, 2)
    for (int t = 0; t < OBS; t++)
        lstm_cell<<<cgrid, THREADS, DYN_SMEM>>>(0, speed + t * 4, pos + t * 4, OBS * 4, 0, t & 1);

    combine_state<<<(BATCH * H + 255) / 256, 256>>>();

    for (int t = 0; t < TDEC; t++) {
        lstm_cell<<<cgrid, THREADS, DYN_SMEM>>>(2, nullptr, nullptr, 4, 1, t & 1);
        proj_kernel<<<BATCH / 8, 256>>>(W_fs, b_fs, W_fc, b_fc, W_emb, b_emb, out, t);
    }
}

// round 7
// speedup vs baseline: 1.8745x; 1.2694x over previous
#include <cuda_runtime.h>
#include <cuda_fp16.h>
#include <cstdint>

#define BATCH 4096
#define OBS 16
#define TDEC 32
#define H 512
#define NG 2048
#define KTOT 1024            // [h_hi | h_lo] x [W | W]  (fp16)
#define KC 64
#define NSTAGE 16            // 1024/64
#define DEPTH 3
#define BM 128
#define BN 128
#define THREADS 256
#define STAGE_BYTES 32768    // A 16K | B 16K
#define DYN_SMEM (DEPTH * STAGE_BYTES)   // 98304

// ---------------- device state ----------------
__device__ __align__(16) float   g_h[2][BATCH * H];        // row-major [m][u]
__device__ __align__(16) float   g_c[2][BATCH * H];
__device__ __align__(16) __half  g_hhi[2][2][BATCH * H];   // [slot][parity]
__device__ __align__(16) __half  g_hlo[2][2][BATCH * H];
__device__ __align__(16) __half  g_Ws[4][NG * 512];        // [(4u+g)][k] fp16
__device__ __align__(16) float   g_Wi[4][NG * 4];
__device__ __align__(16) float   g_bb[4][NG];
__device__ __align__(16) float   g_ls[BATCH * 4];
__device__ __align__(16) float   g_lp[BATCH * 4];

// ---------------- helpers ----------------
__device__ __forceinline__ unsigned su32(const void* p) {
    return (unsigned)__cvta_generic_to_shared(p);
}
__device__ __forceinline__ void cp16(unsigned d, const void* s) {
    asm volatile("cp.async.cg.shared.global [%0], [%1], 16;" :: "r"(d), "l"(s));
}
__device__ __forceinline__ unsigned swz(unsigned o) { return o ^ ((o >> 3) & 0x70); }
__device__ __forceinline__ float sigf(float x) { return 1.f / (1.f + __expf(-x)); }
__device__ __forceinline__ float tanhfast(float x) { return 2.f / (1.f + __expf(-2.f * x)) - 1.f; }

// ---------------- weight prep ----------------
struct WPtrs { const float* Wh[4]; const float* Wi[4]; const float* bb[4]; };

__global__ void prep_weights(WPtrs p) {
    int k = threadIdx.x, j = blockIdx.x, l = blockIdx.y;
    float w = p.Wh[l][j * H + k];
    int pr = 4 * (j & (H - 1)) + (j >> 9);   // 4u + gate
    g_Ws[l][pr * 512 + k] = __float2half(w);
    if (k < 4)  g_Wi[l][pr * 4 + k] = p.Wi[l][j * 4 + k];
    if (k == 0) g_bb[l][pr] = p.bb[l][j];
}

__global__ void init_state(const float* speed, const float* pos) {
    int idx = blockIdx.x * blockDim.x + threadIdx.x;
    if (idx < 2 * BATCH * H) {
        int s = idx / (BATCH * H), i = idx % (BATCH * H);
        g_h[s][i] = 0.f; g_c[s][i] = 0.f;
        g_hhi[s][0][i] = __float2half(0.f);
        g_hlo[s][0][i] = __float2half(0.f);
    }
    if (idx < BATCH * 4) {
        int b = idx >> 2, k = idx & 3;
        g_ls[idx] = speed[b * (OBS * 4) + (OBS - 1) * 4 + k];
        g_lp[idx] = pos[b * (OBS * 4) + (OBS - 1) * 4 + k];
    }
}

__global__ void combine_state() {
    int i = blockIdx.x * blockDim.x + threadIdx.x;
    float hs = g_h[0][i] + g_h[1][i];
    float cs = g_c[0][i] + g_c[1][i];
    g_h[0][i] = hs; g_h[1][i] = hs;
    g_c[0][i] = cs; g_c[1][i] = cs;
    __half hi = __float2half(hs);
    __half lo = __float2half(hs - __half2float(hi));
    g_hhi[0][0][i] = hi; g_hhi[1][0][i] = hi;
    g_hlo[0][0][i] = lo; g_hlo[1][0][i] = lo;
}

// ---------------- fused LSTM cell: fp16 mma.sync, 128x128 tile, 64x32 warp tile ----------------
__global__ void __launch_bounds__(THREADS, 2) lstm_cell(
    int lstm_base, const float* x0, const float* x1, int xstride, int internal_x, int rp)
{
    extern __shared__ char smem[];
    __shared__ float sB[BN];
    __shared__ float sWi[BN * 4];

    const int z = blockIdx.z;
    const int lstm = lstm_base + z;
    const int slot = z;
    const int wp = 1 - rp;
    const int n0 = blockIdx.x * BN;
    const int m0 = blockIdx.y * BM;
    const int tid = threadIdx.x;
    const int lane = tid & 31, warp = tid >> 5;
    const int wmb = (warp & 1) * 64;   // warp m base (2)
    const int wnb = (warp >> 1) * 32;  // warp n base (4)

    const float* x = internal_x ? (z ? g_lp : g_ls) : (z ? x1 : x0);
    const __half* hhi = g_hhi[slot][rp];
    const __half* hlo = g_hlo[slot][rp];
    const __half* Wsp = g_Ws[lstm];

    if (tid < BN) {
        int n = n0 + tid;
        sB[tid] = g_bb[lstm][n];
        #pragma unroll
        for (int k = 0; k < 4; k++) sWi[tid * 4 + k] = g_Wi[lstm][n * 4 + k];
    }

    float acc[4][4][4] = {};

    auto produce = [&](int sp) {
        int kg = sp * KC;
        const __half* asrc = (kg < 512) ? hhi : hlo;
        int kc = kg & 511;
        unsigned sbase = (unsigned)((sp % DEPTH) * STAGE_BYTES);
        #pragma unroll
        for (int r = 0; r < 4; r++) {
            int idx = tid + r * THREADS;
            int row = idx >> 3, seg = idx & 7;
            cp16(su32(smem + sbase + swz(row * 128 + seg * 16)),
                 asrc + (size_t)(m0 + row) * 512 + kc + seg * 8);
        }
        #pragma unroll
        for (int r = 0; r < 4; r++) {
            int idx = tid + r * THREADS;
            int row = idx >> 3, seg = idx & 7;
            cp16(su32(smem + sbase + 16384 + swz(row * 128 + seg * 16)),
                 Wsp + (size_t)(n0 + row) * 512 + kc + seg * 8);
        }
        asm volatile("cp.async.commit_group;");
    };

    produce(0);
    produce(1);

    for (int s = 0; s < NSTAGE; s++) {
        if (s == NSTAGE - 1) asm volatile("cp.async.wait_group 0;");
        else                 asm volatile("cp.async.wait_group 1;");
        __syncthreads();
        if (s + 2 < NSTAGE) produce(s + 2);

        const char* Ab = smem + (s % DEPTH) * STAGE_BYTES;
        const char* Bb = Ab + 16384;
        #pragma unroll
        for (int kk = 0; kk < 4; kk++) {           // k16 step within BK=64
            uint32_t a[4][4];
            #pragma unroll
            for (int im = 0; im < 4; im++) {
                int row = wmb + im * 16 + (lane & 15);
                unsigned off = swz(row * 128 + kk * 32 + ((lane >> 4) << 4));
                asm volatile("ldmatrix.sync.aligned.m8n8.x4.shared.b16 {%0,%1,%2,%3}, [%4];"
                    : "=r"(a[im][0]), "=r"(a[im][1]), "=r"(a[im][2]), "=r"(a[im][3])
                    : "r"(su32(Ab + off)));
            }
            uint32_t b[4][2];
            #pragma unroll
            for (int gp = 0; gp < 2; gp++) {
                int row = wnb + gp * 16 + ((lane >> 4) << 3) + (lane & 7);
                unsigned off = swz(row * 128 + kk * 32 + (((lane >> 3) & 1) << 4));
                asm volatile("ldmatrix.sync.aligned.m8n8.x4.shared.b16 {%0,%1,%2,%3}, [%4];"
                    : "=r"(b[2 * gp][0]), "=r"(b[2 * gp][1]),
                      "=r"(b[2 * gp + 1][0]), "=r"(b[2 * gp + 1][1])
                    : "r"(su32(Bb + off)));
            }
            #pragma unroll
            for (int im = 0; im < 4; im++)
                #pragma unroll
                for (int g = 0; g < 4; g++)
                    asm volatile("mma.sync.aligned.m16n8k16.row.col.f32.f16.f16.f32 "
                        "{%0,%1,%2,%3}, {%4,%5,%6,%7}, {%8,%9}, {%0,%1,%2,%3};"
                        : "+f"(acc[im][g][0]), "+f"(acc[im][g][1]),
                          "+f"(acc[im][g][2]), "+f"(acc[im][g][3])
                        : "r"(a[im][0]), "r"(a[im][1]), "r"(a[im][2]), "r"(a[im][3]),
                          "r"(b[g][0]), "r"(b[g][1]));
        }
    }

    // ---------------- epilogue: transpose gates via smem, fused LSTM pointwise ----------------
    float* Gs = (float*)smem;   // [128][132]
    __syncthreads();
    #pragma unroll
    for (int im = 0; im < 4; im++)
        #pragma unroll
        for (int g = 0; g < 4; g++) {
            int r = wmb + im * 16 + (lane >> 2);
            int c = wnb + g * 8 + 2 * (lane & 3);
            Gs[r * 132 + c]           = acc[im][g][0];
            Gs[r * 132 + c + 1]       = acc[im][g][1];
            Gs[(r + 8) * 132 + c]     = acc[im][g][2];
            Gs[(r + 8) * 132 + c + 1] = acc[im][g][3];
        }
    __syncthreads();

    float* hout = g_h[slot];
    float* cio  = g_c[slot];
    __half* hhiw = g_hhi[slot][wp];
    __half* hlow = g_hlo[slot][wp];
    const int u0g = n0 >> 2;

    #pragma unroll 4
    for (int i = 0; i < 16; i++) {
        int p = tid + THREADS * i;
        int m = p >> 5, ul = p & 31;
        int mg = m0 + m;
        const float4 gv = *(const float4*)&Gs[m * 132 + 4 * ul];
        const float* xr = x + (size_t)mg * xstride;
        float xv0 = xr[0], xv1 = xr[1], xv2 = xr[2], xv3 = xr[3];
        float gate[4] = { gv.x, gv.y, gv.z, gv.w };
        #pragma unroll
        for (int j = 0; j < 4; j++) {
            int nn = 4 * ul + j;
            gate[j] += sB[nn] + xv0 * sWi[nn * 4 + 0] + xv1 * sWi[nn * 4 + 1]
                              + xv2 * sWi[nn * 4 + 2] + xv3 * sWi[nn * 4 + 3];
        }
        float iv = sigf(gate[0]);
        float fv = sigf(gate[1]);
        float gg = tanhfast(gate[2]);
        float ov = sigf(gate[3]);
        size_t ci = (size_t)mg * H + u0g + ul;
        float cn = fv * cio[ci] + iv * gg;
        float hn = ov * tanhfast(cn);
        cio[ci] = cn;
        hout[ci] = hn;
        __half hib = __float2half(hn);
        hhiw[ci] = hib;
        hlow[ci] = __float2half(hn - __half2float(hib));
    }
}

// ---------------- decoder projections + feedback ----------------
__global__ void proj_kernel(const float* W_fs, const float* b_fs,
                            const float* W_fc, const float* b_fc,
                            const float* W_emb, const float* b_emb,
                            float* out, int t)
{
    int warp = threadIdx.x >> 5, lane = threadIdx.x & 31;
    int b = blockIdx.x * 8 + warp;
    float a0 = 0, a1 = 0, a2 = 0, a3 = 0, a4 = 0, a5 = 0;
    const float* hs = g_h[0] + (size_t)b * H;
    const float* hi = g_h[1] + (size_t)b * H;
    for (int k = lane; k < H; k += 32) {
        float vs = hs[k], vi = hi[k];
        a0 += vs * W_fs[k];
        a1 += vs * W_fs[H + k];
        a2 += vs * W_fs[2 * H + k];
        a3 += vs * W_fs[3 * H + k];
        a4 += vi * W_fc[k];
        a5 += vi * W_fc[H + k];
    }
    #pragma unroll
    for (int o = 16; o; o >>= 1) {
        a0 += __shfl_down_sync(0xffffffffu, a0, o);
        a1 += __shfl_down_sync(0xffffffffu, a1, o);
        a2 += __shfl_down_sync(0xffffffffu, a2, o);
        a3 += __shfl_down_sync(0xffffffffu, a3, o);
        a4 += __shfl_down_sync(0xffffffffu, a4, o);
        a5 += __shfl_down_sync(0xffffffffu, a5, o);
    }
    if (lane == 0) {
        float4 spv;
        spv.x = fminf(fmaxf(a0 + b_fs[0], -100.f), 100.f);
        spv.y = fminf(fmaxf(a1 + b_fs[1], -100.f), 100.f);
        spv.z = fminf(fmaxf(a2 + b_fs[2], -100.f), 100.f);
        spv.w = fminf(fmaxf(a3 + b_fs[3], -100.f), 100.f);
        float it0 = fmaxf(a4 + b_fc[0], 0.f);
        float it1 = fmaxf(a5 + b_fc[1], 0.f);
        *(float4*)&out[((size_t)b * TDEC + t) * 4] = spv;
        *(float4*)&g_ls[b * 4] = spv;
        float4 lpv;
        lpv.x = fmaxf(W_emb[0] * it0 + W_emb[1] * it1 + b_emb[0], 0.f);
        lpv.y = fmaxf(W_emb[2] * it0 + W_emb[3] * it1 + b_emb[1], 0.f);
        lpv.z = fmaxf(W_emb[4] * it0 + W_emb[5] * it1 + b_emb[2], 0.f);
        lpv.w = fmaxf(W_emb[6] * it0 + W_emb[7] * it1 + b_emb[3], 0.f);
        *(float4*)&g_lp[b * 4] = lpv;
        if (t == TDEC - 1) {
            float mx = fmaxf(it0, it1);
            float e0 = expf(it0 - mx), e1 = expf(it1 - mx);
            float s = e0 + e1;
            out[(size_t)BATCH * TDEC * 4 + b * 2]     = e0 / s;
            out[(size_t)BATCH * TDEC * 4 + b * 2 + 1] = e1 / s;
        }
    }
}

// ---------------- launch ----------------
extern "C" void kernel_launch(void* const* d_in, const int* in_sizes, int n_in,
                              void* d_out, int out_size)
{
    const float* speed = (const float*)d_in[0];
    const float* pos   = (const float*)d_in[1];
    WPtrs wpt;
    wpt.Wi[0] = (const float*)d_in[2];  wpt.Wh[0] = (const float*)d_in[3];  wpt.bb[0] = (const float*)d_in[4];
    wpt.Wi[1] = (const float*)d_in[5];  wpt.Wh[1] = (const float*)d_in[6];  wpt.bb[1] = (const float*)d_in[7];
    wpt.Wi[2] = (const float*)d_in[8];  wpt.Wh[2] = (const float*)d_in[9];  wpt.bb[2] = (const float*)d_in[10];
    wpt.Wi[3] = (const float*)d_in[11]; wpt.Wh[3] = (const float*)d_in[12]; wpt.bb[3] = (const float*)d_in[13];
    const float* W_fs  = (const float*)d_in[14];
    const float* b_fs  = (const float*)d_in[15];
    const float* W_fc  = (const float*)d_in[16];
    const float* b_fc  = (const float*)d_in[17];
    const float* W_emb = (const float*)d_in[18];
    const float* b_emb = (const float*)d_in[19];
    float* out = (float*)d_out;

    cudaFuncSetAttribute(lstm_cell, cudaFuncAttributeMaxDynamicSharedMemorySize, DYN_SMEM);

    prep_weights<<<dim3(NG, 4), 512>>>(wpt);
    init_state<<<(2 * BATCH * H + 255) / 256, 256>>>(speed, pos);

    dim3 cgrid(NG / BN, BATCH / BM, 2);   // (16, 32, 2)
    for (int t = 0; t < OBS; t++)
        lstm_cell<<<cgrid, THREADS, DYN_SMEM>>>(0, speed + t * 4, pos + t * 4, OBS * 4, 0, t & 1);

    combine_state<<<(BATCH * H + 255) / 256, 256>>>();

    for (int t = 0; t < TDEC; t++) {
        lstm_cell<<<cgrid, THREADS, DYN_SMEM>>>(2, nullptr, nullptr, 4, 1, t & 1);
        proj_kernel<<<BATCH / 8, 256>>>(W_fs, b_fs, W_fc, b_fc, W_emb, b_emb, out, t);
    }
}

// round 8
// speedup vs baseline: 2.5725x; 1.3724x over previous
#include <cuda_runtime.h>
#include <cuda_fp16.h>
#include <cstdint>

#define BATCH 4096
#define OBS 16
#define TDEC 32
#define H 512
#define NG 2048
#define KTOT 512             // plain fp16 GEMM
#define KC 64
#define NSTAGE 8             // 512/64
#define DEPTH 3
#define BM 128
#define BN 128
#define THREADS 256
#define STAGE_BYTES 32768    // A 16K | B 16K
#define DYN_SMEM (DEPTH * STAGE_BYTES)   // 98304

// ---------------- device state ----------------
__device__ __align__(16) float   g_h[2][BATCH * H];        // fp32 h (for proj), row-major [m][u]
__device__ __align__(16) float   g_c[2][BATCH * H];
__device__ __align__(16) __half  g_hh[2][2][BATCH * H];    // fp16 h, [slot][parity]
__device__ __align__(16) __half  g_Ws[4][NG * 512];        // [(4u+g)][k] fp16
__device__ __align__(16) float   g_Wi[4][NG * 4];
__device__ __align__(16) float   g_bb[4][NG];
__device__ __align__(16) float   g_ls[BATCH * 4];
__device__ __align__(16) float   g_lp[BATCH * 4];

// ---------------- helpers ----------------
__device__ __forceinline__ unsigned su32(const void* p) {
    return (unsigned)__cvta_generic_to_shared(p);
}
__device__ __forceinline__ void cp16(unsigned d, const void* s) {
    asm volatile("cp.async.cg.shared.global [%0], [%1], 16;" :: "r"(d), "l"(s));
}
__device__ __forceinline__ unsigned swz(unsigned o) { return o ^ ((o >> 3) & 0x70); }
__device__ __forceinline__ float sigf(float x) { return 1.f / (1.f + __expf(-x)); }
__device__ __forceinline__ float tanhfast(float x) { return 2.f / (1.f + __expf(-2.f * x)) - 1.f; }

// ---------------- weight prep ----------------
struct WPtrs { const float* Wh[4]; const float* Wi[4]; const float* bb[4]; };

__global__ void prep_weights(WPtrs p) {
    int k = threadIdx.x, j = blockIdx.x, l = blockIdx.y;
    float w = p.Wh[l][j * H + k];
    int pr = 4 * (j & (H - 1)) + (j >> 9);   // 4u + gate
    g_Ws[l][pr * 512 + k] = __float2half(w);
    if (k < 4)  g_Wi[l][pr * 4 + k] = p.Wi[l][j * 4 + k];
    if (k == 0) g_bb[l][pr] = p.bb[l][j];
}

__global__ void init_state(const float* speed, const float* pos) {
    int idx = blockIdx.x * blockDim.x + threadIdx.x;
    if (idx < 2 * BATCH * H) {
        int s = idx / (BATCH * H), i = idx % (BATCH * H);
        g_h[s][i] = 0.f; g_c[s][i] = 0.f;
        g_hh[s][0][i] = __float2half(0.f);
    }
    if (idx < BATCH * 4) {
        int b = idx >> 2, k = idx & 3;
        g_ls[idx] = speed[b * (OBS * 4) + (OBS - 1) * 4 + k];
        g_lp[idx] = pos[b * (OBS * 4) + (OBS - 1) * 4 + k];
    }
}

__global__ void combine_state() {
    int i = blockIdx.x * blockDim.x + threadIdx.x;
    float hs = g_h[0][i] + g_h[1][i];
    float cs = g_c[0][i] + g_c[1][i];
    g_h[0][i] = hs; g_h[1][i] = hs;
    g_c[0][i] = cs; g_c[1][i] = cs;
    __half hv = __float2half(hs);
    g_hh[0][0][i] = hv; g_hh[1][0][i] = hv;
}

// ---------------- fused LSTM cell: fp16 mma.sync, 128x128 tile, 64x32 warp tile ----------------
__global__ void __launch_bounds__(THREADS, 2) lstm_cell(
    int lstm_base, const float* x0, const float* x1, int xstride, int internal_x, int rp)
{
    extern __shared__ char smem[];
    __shared__ float sB[BN];
    __shared__ float sWi[BN * 4];

    const int z = blockIdx.z;
    const int lstm = lstm_base + z;
    const int slot = z;
    const int wp = 1 - rp;
    const int n0 = blockIdx.x * BN;
    const int m0 = blockIdx.y * BM;
    const int tid = threadIdx.x;
    const int lane = tid & 31, warp = tid >> 5;
    const int wmb = (warp & 1) * 64;   // warp m base (2)
    const int wnb = (warp >> 1) * 32;  // warp n base (4)

    const float* x = internal_x ? (z ? g_lp : g_ls) : (z ? x1 : x0);
    const __half* hh = g_hh[slot][rp];
    const __half* Wsp = g_Ws[lstm];

    if (tid < BN) {
        int n = n0 + tid;
        sB[tid] = g_bb[lstm][n];
        #pragma unroll
        for (int k = 0; k < 4; k++) sWi[tid * 4 + k] = g_Wi[lstm][n * 4 + k];
    }

    float acc[4][4][4] = {};

    auto produce = [&](int sp) {
        int kc = sp * KC;
        unsigned sbase = (unsigned)((sp % DEPTH) * STAGE_BYTES);
        #pragma unroll
        for (int r = 0; r < 4; r++) {
            int idx = tid + r * THREADS;
            int row = idx >> 3, seg = idx & 7;
            cp16(su32(smem + sbase + swz(row * 128 + seg * 16)),
                 hh + (size_t)(m0 + row) * 512 + kc + seg * 8);
        }
        #pragma unroll
        for (int r = 0; r < 4; r++) {
            int idx = tid + r * THREADS;
            int row = idx >> 3, seg = idx & 7;
            cp16(su32(smem + sbase + 16384 + swz(row * 128 + seg * 16)),
                 Wsp + (size_t)(n0 + row) * 512 + kc + seg * 8);
        }
        asm volatile("cp.async.commit_group;");
    };

    produce(0);
    produce(1);

    for (int s = 0; s < NSTAGE; s++) {
        if (s == NSTAGE - 1) asm volatile("cp.async.wait_group 0;");
        else                 asm volatile("cp.async.wait_group 1;");
        __syncthreads();
        if (s + 2 < NSTAGE) produce(s + 2);

        const char* Ab = smem + (s % DEPTH) * STAGE_BYTES;
        const char* Bb = Ab + 16384;
        #pragma unroll
        for (int kk = 0; kk < 4; kk++) {           // k16 step within BK=64
            uint32_t a[4][4];
            #pragma unroll
            for (int im = 0; im < 4; im++) {
                int row = wmb + im * 16 + (lane & 15);
                unsigned off = swz(row * 128 + kk * 32 + ((lane >> 4) << 4));
                asm volatile("ldmatrix.sync.aligned.m8n8.x4.shared.b16 {%0,%1,%2,%3}, [%4];"
                    : "=r"(a[im][0]), "=r"(a[im][1]), "=r"(a[im][2]), "=r"(a[im][3])
                    : "r"(su32(Ab + off)));
            }
            uint32_t b[4][2];
            #pragma unroll
            for (int gp = 0; gp < 2; gp++) {
                int row = wnb + gp * 16 + ((lane >> 4) << 3) + (lane & 7);
                unsigned off = swz(row * 128 + kk * 32 + (((lane >> 3) & 1) << 4));
                asm volatile("ldmatrix.sync.aligned.m8n8.x4.shared.b16 {%0,%1,%2,%3}, [%4];"
                    : "=r"(b[2 * gp][0]), "=r"(b[2 * gp][1]),
                      "=r"(b[2 * gp + 1][0]), "=r"(b[2 * gp + 1][1])
                    : "r"(su32(Bb + off)));
            }
            #pragma unroll
            for (int im = 0; im < 4; im++)
                #pragma unroll
                for (int g = 0; g < 4; g++)
                    asm volatile("mma.sync.aligned.m16n8k16.row.col.f32.f16.f16.f32 "
                        "{%0,%1,%2,%3}, {%4,%5,%6,%7}, {%8,%9}, {%0,%1,%2,%3};"
                        : "+f"(acc[im][g][0]), "+f"(acc[im][g][1]),
                          "+f"(acc[im][g][2]), "+f"(acc[im][g][3])
                        : "r"(a[im][0]), "r"(a[im][1]), "r"(a[im][2]), "r"(a[im][3]),
                          "r"(b[g][0]), "r"(b[g][1]));
        }
    }

    // ---------------- epilogue: transpose gates via smem, fused LSTM pointwise ----------------
    float* Gs = (float*)smem;   // [128][132]
    __syncthreads();
    #pragma unroll
    for (int im = 0; im < 4; im++)
        #pragma unroll
        for (int g = 0; g < 4; g++) {
            int r = wmb + im * 16 + (lane >> 2);
            int c = wnb + g * 8 + 2 * (lane & 3);
            Gs[r * 132 + c]           = acc[im][g][0];
            Gs[r * 132 + c + 1]       = acc[im][g][1];
            Gs[(r + 8) * 132 + c]     = acc[im][g][2];
            Gs[(r + 8) * 132 + c + 1] = acc[im][g][3];
        }
    __syncthreads();

    float* hout = g_h[slot];
    float* cio  = g_c[slot];
    __half* hhw = g_hh[slot][wp];
    const int u0g = n0 >> 2;

    #pragma unroll 4
    for (int i = 0; i < 16; i++) {
        int p = tid + THREADS * i;
        int m = p >> 5, ul = p & 31;
        int mg = m0 + m;
        const float4 gv = *(const float4*)&Gs[m * 132 + 4 * ul];
        const float* xr = x + (size_t)mg * xstride;
        float xv0 = xr[0], xv1 = xr[1], xv2 = xr[2], xv3 = xr[3];
        float gate[4] = { gv.x, gv.y, gv.z, gv.w };
        #pragma unroll
        for (int j = 0; j < 4; j++) {
            int nn = 4 * ul + j;
            gate[j] += sB[nn] + xv0 * sWi[nn * 4 + 0] + xv1 * sWi[nn * 4 + 1]
                              + xv2 * sWi[nn * 4 + 2] + xv3 * sWi[nn * 4 + 3];
        }
        float iv = sigf(gate[0]);
        float fv = sigf(gate[1]);
        float gg = tanhfast(gate[2]);
        float ov = sigf(gate[3]);
        size_t ci = (size_t)mg * H + u0g + ul;
        float cn = fv * cio[ci] + iv * gg;
        float hn = ov * tanhfast(cn);
        cio[ci] = cn;
        hout[ci] = hn;
        hhw[ci] = __float2half(hn);
    }
}

// ---------------- decoder projections + feedback ----------------
__global__ void proj_kernel(const float* W_fs, const float* b_fs,
                            const float* W_fc, const float* b_fc,
                            const float* W_emb, const float* b_emb,
                            float* out, int t)
{
    int warp = threadIdx.x >> 5, lane = threadIdx.x & 31;
    int b = blockIdx.x * 8 + warp;
    float a0 = 0, a1 = 0, a2 = 0, a3 = 0, a4 = 0, a5 = 0;
    const float* hs = g_h[0] + (size_t)b * H;
    const float* hi = g_h[1] + (size_t)b * H;
    for (int k = lane; k < H; k += 32) {
        float vs = hs[k], vi = hi[k];
        a0 += vs * W_fs[k];
        a1 += vs * W_fs[H + k];
        a2 += vs * W_fs[2 * H + k];
        a3 += vs * W_fs[3 * H + k];
        a4 += vi * W_fc[k];
        a5 += vi * W_fc[H + k];
    }
    #pragma unroll
    for (int o = 16; o; o >>= 1) {
        a0 += __shfl_down_sync(0xffffffffu, a0, o);
        a1 += __shfl_down_sync(0xffffffffu, a1, o);
        a2 += __shfl_down_sync(0xffffffffu, a2, o);
        a3 += __shfl_down_sync(0xffffffffu, a3, o);
        a4 += __shfl_down_sync(0xffffffffu, a4, o);
        a5 += __shfl_down_sync(0xffffffffu, a5, o);
    }
    if (lane == 0) {
        float4 spv;
        spv.x = fminf(fmaxf(a0 + b_fs[0], -100.f), 100.f);
        spv.y = fminf(fmaxf(a1 + b_fs[1], -100.f), 100.f);
        spv.z = fminf(fmaxf(a2 + b_fs[2], -100.f), 100.f);
        spv.w = fminf(fmaxf(a3 + b_fs[3], -100.f), 100.f);
        float it0 = fmaxf(a4 + b_fc[0], 0.f);
        float it1 = fmaxf(a5 + b_fc[1], 0.f);
        *(float4*)&out[((size_t)b * TDEC + t) * 4] = spv;
        *(float4*)&g_ls[b * 4] = spv;
        float4 lpv;
        lpv.x = fmaxf(W_emb[0] * it0 + W_emb[1] * it1 + b_emb[0], 0.f);
        lpv.y = fmaxf(W_emb[2] * it0 + W_emb[3] * it1 + b_emb[1], 0.f);
        lpv.z = fmaxf(W_emb[4] * it0 + W_emb[5] * it1 + b_emb[2], 0.f);
        lpv.w = fmaxf(W_emb[6] * it0 + W_emb[7] * it1 + b_emb[3], 0.f);
        *(float4*)&g_lp[b * 4] = lpv;
        if (t == TDEC - 1) {
            float mx = fmaxf(it0, it1);
            float e0 = expf(it0 - mx), e1 = expf(it1 - mx);
            float s = e0 + e1;
            out[(size_t)BATCH * TDEC * 4 + b * 2]     = e0 / s;
            out[(size_t)BATCH * TDEC * 4 + b * 2 + 1] = e1 / s;
        }
    }
}

// ---------------- launch ----------------
extern "C" void kernel_launch(void* const* d_in, const int* in_sizes, int n_in,
                              void* d_out, int out_size)
{
    const float* speed = (const float*)d_in[0];
    const float* pos   = (const float*)d_in[1];
    WPtrs wpt;
    wpt.Wi[0] = (const float*)d_in[2];  wpt.Wh[0] = (const float*)d_in[3];  wpt.bb[0] = (const float*)d_in[4];
    wpt.Wi[1] = (const float*)d_in[5];  wpt.Wh[1] = (const float*)d_in[6];  wpt.bb[1] = (const float*)d_in[7];
    wpt.Wi[2] = (const float*)d_in[8];  wpt.Wh[2] = (const float*)d_in[9];  wpt.bb[2] = (const float*)d_in[10];
    wpt.Wi[3] = (const float*)d_in[11]; wpt.Wh[3] = (const float*)d_in[12]; wpt.bb[3] = (const float*)d_in[13];
    const float* W_fs  = (const float*)d_in[14];
    const float* b_fs  = (const float*)d_in[15];
    const float* W_fc  = (const float*)d_in[16];
    const float* b_fc  = (const float*)d_in[17];
    const float* W_emb = (const float*)d_in[18];
    const float* b_emb = (const float*)d_in[19];
    float* out = (float*)d_out;

    cudaFuncSetAttribute(lstm_cell, cudaFuncAttributeMaxDynamicSharedMemorySize, DYN_SMEM);

    prep_weights<<<dim3(NG, 4), 512>>>(wpt);
    init_state<<<(2 * BATCH * H + 255) / 256, 256>>>(speed, pos);

    dim3 cgrid(NG / BN, BATCH / BM, 2);   // (16, 32, 2)
    for (int t = 0; t < OBS; t++)
        lstm_cell<<<cgrid, THREADS, DYN_SMEM>>>(0, speed + t * 4, pos + t * 4, OBS * 4, 0, t & 1);

    combine_state<<<(BATCH * H + 255) / 256, 256>>>();

    for (int t = 0; t < TDEC; t++) {
        lstm_cell<<<cgrid, THREADS, DYN_SMEM>>>(2, nullptr, nullptr, 4, 1, t & 1);
        proj_kernel<<<BATCH / 8, 256>>>(W_fs, b_fs, W_fc, b_fc, W_emb, b_emb, out, t);
    }
}